// round 17
// baseline (speedup 1.0000x reference)
#include <cuda_runtime.h>
#include <cstdint>

#define BB 4
#define CC 32
#define PP 65536
#define KK 256
#define PCH 1024
#define CHUNKS 2
#define WINPX (PCH * CHUNKS)         // 2048
#define NWIN (PP / WINPX)            // 32
#define GRID (BB * NWIN)             // 128
#define THREADS 1024
#define FSR 36                       // F row stride (floats) = 144 B
#define TROW 36

#define F_F    (PCH * FSR)           // 36864
#define A3_F   (3 * PCH * 4)         // 12288
#define SMEM_FLOATS (F_F + A3_F + 2 * PCH + KK + KK + 1)
#define SMEM_BYTES  (SMEM_FLOATS * 4)   // ~206 KB -> 1 CTA/SM, 32 warps

__device__ __align__(16) float g_fsum[BB * KK * TROW];  // [b][k][c<32], wsum@32; zero at load
__device__ unsigned g_done;

typedef unsigned long long u64t;

__device__ __forceinline__ void fma2(u64t& d, u64t a, u64t b) {
    asm("fma.rn.f32x2 %0, %1, %2, %0;" : "+l"(d) : "l"(a), "l"(b));
}
__device__ __forceinline__ u64t pack2(float w) {
    u64t r; unsigned u = __float_as_uint(w);
    asm("mov.b64 %0, {%1, %1};" : "=l"(r) : "r"(u));
    return r;
}
__device__ __forceinline__ void unpack2(u64t v, float& lo, float& hi) {
    unsigned a, b;
    asm("mov.b64 {%0, %1}, %2;" : "=r"(a), "=r"(b) : "l"(v));
    lo = __uint_as_float(a); hi = __uint_as_float(b);
}
__device__ __forceinline__ u64t lo64(float4 v) {
    u64t r; asm("mov.b64 %0, {%1, %2};" : "=l"(r) : "f"(v.x), "f"(v.y)); return r;
}
__device__ __forceinline__ u64t hi64(float4 v) {
    u64t r; asm("mov.b64 %0, {%1, %2};" : "=l"(r) : "f"(v.z), "f"(v.w)); return r;
}

__global__ __launch_bounds__(THREADS, 1)
void spix_main(const float* __restrict__ feats,
               const float* __restrict__ assoc,
               const int*   __restrict__ idxmap,
               float* __restrict__ out) {
    extern __shared__ float sm[];
    float* F_sh  = sm;                        // [1024][36] pixel-major (32 used)
    float* A3    = sm + F_F;                  // [3][1024][4]: A3[d][p][t] = w[3d+t]
    int2*  plist = (int2*)(A3 + A3_F);        // [1024] {4*pl - ix, 144*pl (bytes)}
    int*   cnt   = (int*)(plist + PCH);       // [256]
    int*   offs  = cnt + KK;                  // [257]

    const int b    = blockIdx.x >> 5;
    const int s    = blockIdx.x & 31;
    const int tid  = threadIdx.x;
    const int wid  = tid >> 5;
    const int lane = tid & 31;
    const int g    = lane >> 3;               // entry group 0..3
    const int cl8  = lane & 7;                // channel quad (4*cl8 .. 4*cl8+3)
    const int ky   = wid >> 1;
    const int par  = wid & 1;

    // persistent accumulators: 2 packed channel-pairs + wsum per owned bin
    u64t  accA[8], accB[8];
    float aw[8];
#pragma unroll
    for (int i = 0; i < 8; i++) { accA[i] = 0ull; accB[i] = 0ull; aw[i] = 0.f; }

    const char* Fb = (const char*)F_sh + 16 * cl8;   // + 144*pl per entry (16B aligned)

    for (int ch = 0; ch < CHUNKS; ch++) {
        const int p0 = s * WINPX + ch * PCH;

        if (tid < KK) cnt[tid] = 0;
        __syncthreads();   // fences prev-chunk gather before F/A3/plist reuse

        // ---- stage F: thread = pixel; coalesced LDG.32 -> conflict-free STS.128 ----
        {
            const float* src = feats + (size_t)b * CC * PP + p0 + tid;
            float4* dst = (float4*)(F_sh + tid * FSR);
#pragma unroll
            for (int q = 0; q < 8; q++) {
                float4 v;
                v.x = src[(size_t)(4 * q + 0) * PP];
                v.y = src[(size_t)(4 * q + 1) * PP];
                v.z = src[(size_t)(4 * q + 2) * PP];
                v.w = src[(size_t)(4 * q + 3) * PP];
                dst[q] = v;
            }
        }
        // ---- stage A3: thread = pixel; 9 LDG.32 -> 3 STS.128 ----
        {
            const float* src = assoc + (size_t)b * 9 * PP + p0 + tid;
            float w[9];
#pragma unroll
            for (int j = 0; j < 9; j++) w[j] = src[(size_t)j * PP];
#pragma unroll
            for (int d = 0; d < 3; d++)
                ((float4*)A3)[d * PCH + tid] =
                    make_float4(w[3 * d + 0], w[3 * d + 1], w[3 * d + 2], 0.f);
        }

        // ---- count / scan / place (cheap base-bin counting sort) ----
        const int idxA = idxmap[(size_t)b * PP + p0 + tid];
        atomicAdd(&cnt[idxA], 1);
        __syncthreads();

        if (wid == 0) {
            int running = 0;
            for (int gi = 0; gi < KK / 32; gi++) {
                const int v = cnt[gi * 32 + lane];
                int incl = v;
#pragma unroll
                for (int d = 1; d < 32; d <<= 1) {
                    int n = __shfl_up_sync(0xffffffffu, incl, d);
                    if (lane >= d) incl += n;
                }
                offs[gi * 32 + lane] = running + incl - v;
                running += __shfl_sync(0xffffffffu, incl, 31);
            }
            if (lane == 0) offs[KK] = PCH;
        }
        __syncthreads();
        if (tid < KK) cnt[tid] = offs[tid];
        __syncthreads();
        {
            const int slot = atomicAdd(&cnt[idxA], 1);
            plist[slot] = make_int2(4 * tid - (idxA & 15), 144 * tid);
        }
        __syncthreads();

        // ---- gather: warp owns bins (ky, kx=2*kxi+par); 4 entries/iter via quarters ----
#pragma unroll
        for (int kxi = 0; kxi < 8; kxi++) {
            const int kx = 2 * kxi + par;
            u64t  aA = 0ull, aB = 0ull;
            float w_s = 0.f;
            const int xlo = kx > 0  ? kx - 1 : 0;
            const int xhi = kx < 15 ? kx + 1 : 15;
#pragma unroll
            for (int dy = -1; dy <= 1; dy++) {
                const int sy = ky + dy;
                if (sy < 0 || sy > 15) continue;
                const int d = 1 - dy;
                const int beg = offs[sy * 16 + xlo];
                const int end = offs[sy * 16 + xhi + 1];
                const float* Aw = A3 + (d * (PCH * 4) + kx + 1);
                int e = beg;
                for (int it = (end - beg) >> 2; it > 0; --it, e += 4) {
                    const int2 pr = plist[e + g];              // LDS.64: 4 addrs, 1 wf
                    const float w = Aw[pr.x];                  // LDS.32 broadcast/quarter
                    const u64t wp = pack2(w);
                    const float4 f4 = *(const float4*)(Fb + pr.y);  // LDS.128 conflict-free
                    fma2(aA, wp, lo64(f4));
                    fma2(aB, wp, hi64(f4));
                    w_s += w;
                }
                const int rem = end - e;                       // 0..3
                if (rem) {
                    const bool vv = g < rem;
                    const int2 pr = plist[vv ? e + g : e];     // always valid run entry
                    float w = Aw[pr.x];                        // in-bounds even when !vv
                    if (!vv) w = 0.f;
                    const u64t wp = pack2(w);
                    const float4 f4 = *(const float4*)(Fb + pr.y);
                    fma2(aA, wp, lo64(f4));
                    fma2(aB, wp, hi64(f4));
                    w_s += w;
                }
            }
            fma2(accA[kxi], pack2(1.0f), aA);
            fma2(accB[kxi], pack2(1.0f), aB);
            aw[kxi] += w_s;
        }
    }

    // ---- flush: merge quarters via shfl (xor 8, 16), fire-and-forget REDG ----
#pragma unroll
    for (int kxi = 0; kxi < 8; kxi++) {
        float a0, a1, a2, a3;
        unpack2(accA[kxi], a0, a1);
        unpack2(accB[kxi], a2, a3);
        float awt = aw[kxi];
#pragma unroll
        for (int d = 8; d <= 16; d <<= 1) {
            a0  += __shfl_xor_sync(0xffffffffu, a0, d);
            a1  += __shfl_xor_sync(0xffffffffu, a1, d);
            a2  += __shfl_xor_sync(0xffffffffu, a2, d);
            a3  += __shfl_xor_sync(0xffffffffu, a3, d);
            awt += __shfl_xor_sync(0xffffffffu, awt, d);
        }
        const int k = ky * 16 + 2 * kxi + par;
        float* gb = &g_fsum[(size_t)(b * KK + k) * TROW];
        if (lane < 8) {
            atomicAdd(gb + 4 * cl8 + 0, a0);
            atomicAdd(gb + 4 * cl8 + 1, a1);
            atomicAdd(gb + 4 * cl8 + 2, a2);
            atomicAdd(gb + 4 * cl8 + 3, a3);
        } else if (lane == 8) {
            atomicAdd(gb + 32, awt);
        }
    }

    // ---- fused epilogue: last CTA normalizes, writes out, re-zeroes scratch ----
    __shared__ unsigned s_rank;
    __threadfence();
    __syncthreads();
    if (tid == 0) s_rank = atomicAdd(&g_done, 1u);
    __syncthreads();
    if (s_rank == GRID - 1) {
        __threadfence();
        for (int i = tid; i < BB * KK * CC; i += THREADS) {
            const int c  = i & 31;
            const int bk = i >> 5;
            const float ws = g_fsum[(size_t)bk * TROW + 32];
            const float fs = g_fsum[(size_t)bk * TROW + c];
            const int k = bk & 255, bb2 = bk >> 8;
            out[((size_t)(bb2 * CC) + c) * KK + k] = (ws > 1e-16f) ? fs / ws : 0.f;
        }
        __syncthreads();
        for (int i = tid; i < BB * KK * TROW; i += THREADS) g_fsum[i] = 0.f;
        if (tid == 0) g_done = 0;
    }
}

extern "C" void kernel_launch(void* const* d_in, const int* in_sizes, int n_in,
                              void* d_out, int out_size) {
    const float* feats  = (const float*)d_in[0];
    const float* assoc  = (const float*)d_in[1];
    const int*   idxmap = (const int*)d_in[2];

    static int configured = 0;
    if (!configured) {
        cudaFuncSetAttribute(spix_main, cudaFuncAttributeMaxDynamicSharedMemorySize,
                             SMEM_BYTES);
        configured = 1;
    }
    spix_main<<<GRID, THREADS, SMEM_BYTES>>>(feats, assoc, idxmap, (float*)d_out);
}